// round 7
// baseline (speedup 1.0000x reference)
#include <cuda_runtime.h>
#include <cuda_bf16.h>
#include <cstdint>
#include <math.h>

#define L_SEQ 4096
#define H_DIM 1024
#define E_DIM 1024
#define H3    3072
#define T_DIM 512

#define RNN_NCTA 128
#define NIDX 16
#define RNN_THREADS 320          // 8 compute warps + 2 poller warps

typedef unsigned long long ull;

// ---------------- device scratch ----------------
__device__ float g_gx[4][L_SEQ][H3];          // [sent*2+dir][t][3H]
__device__ float g_h[2][2][2][H_DIM];         // [buf][dir][sent][H]
__device__ float g_hs[4];
__device__ unsigned int g_flag[2][RNN_NCTA * 32];   // [sentence][cta], 128B padded

// ---------------- helpers ----------------
__device__ __forceinline__ unsigned tf32_of(float f) {
  unsigned r; asm("cvt.rna.tf32.f32 %0, %1;" : "=r"(r) : "f"(f)); return r;
}
__device__ __forceinline__ void mma_tf32(float* c, const unsigned* a, const unsigned* b) {
  asm volatile("mma.sync.aligned.m16n8k8.row.col.f32.tf32.tf32.f32 "
    "{%0,%1,%2,%3},{%4,%5,%6,%7},{%8,%9},{%0,%1,%2,%3};"
    : "+f"(c[0]), "+f"(c[1]), "+f"(c[2]), "+f"(c[3])
    : "r"(a[0]), "r"(a[1]), "r"(a[2]), "r"(a[3]), "r"(b[0]), "r"(b[1]));
}
__device__ __forceinline__ float sigm(float x) { return 1.f / (1.f + __expf(-x)); }

__device__ __forceinline__ void ffma2(ull& d, ull a, ull b) {
  asm("fma.rn.f32x2 %0, %1, %2, %0;" : "+l"(d) : "l"(a), "l"(b));
}
__device__ __forceinline__ float pairsum(ull v) {
  float x, y;
  asm("mov.b64 {%0,%1}, %2;" : "=f"(x), "=f"(y) : "l"(v));
  return x + y;
}
__device__ __forceinline__ unsigned ld_acq(const unsigned* p) {
  unsigned v;
  asm volatile("ld.acquire.gpu.u32 %0, [%1];" : "=r"(v) : "l"(p) : "memory");
  return v;
}
__device__ __forceinline__ void st_rel(unsigned* p, unsigned v) {
  asm volatile("st.release.gpu.u32 [%0], %1;" :: "l"(p), "r"(v) : "memory");
}
__device__ __forceinline__ unsigned ld_acq_cta(const unsigned* p) {
  unsigned v;
  asm volatile("ld.acquire.cta.u32 %0, [%1];" : "=r"(v) : "l"(p) : "memory");
  return v;
}
__device__ __forceinline__ void st_rel_cta(unsigned* p, unsigned v) {
  asm volatile("st.release.cta.u32 [%0], %1;" :: "l"(p), "r"(v) : "memory");
}
__device__ __forceinline__ float4 ldcg_f4(const float4* p) {
  float4 v;
  asm volatile("ld.global.cg.v4.f32 {%0,%1,%2,%3}, [%4];"
    : "=f"(v.x), "=f"(v.y), "=f"(v.z), "=f"(v.w) : "l"(p));
  return v;
}
__device__ __forceinline__ void bar2() {       // compute warps only (256 threads)
  asm volatile("bar.sync 2, 256;" ::: "memory");
}

// ---------------- init ----------------
__global__ void init_kernel(const float* __restrict__ hidden) {
  int i = blockIdx.x * blockDim.x + threadIdx.x;
  if (i < 2 * RNN_NCTA * 32) ((unsigned*)g_flag)[i] = 0u;
  if (i < 4) g_hs[i] = 0.f;
  if (i < 2 * H_DIM) {
    int d = i / H_DIM, j = i % H_DIM;
    g_h[0][d][0][j] = hidden[i];
    g_h[0][d][1][j] = hidden[i];
  }
}

// ---------------- gx GEMM ----------------
__global__ __launch_bounds__(256) void gemm_gx(
    const int* __restrict__ sA, const int* __restrict__ sB,
    const float* __restrict__ emb,
    const float* __restrict__ wf, const float* __restrict__ wr,
    const float* __restrict__ bihf, const float* __restrict__ bhhf,
    const float* __restrict__ bihr, const float* __restrict__ bhhr) {
  __shared__ float As[128][17];
  __shared__ float Bs[128][17];

  int z = blockIdx.z;
  const int*   toks = (z >> 1) ? sB : sA;
  const float* W    = (z & 1) ? wr   : wf;
  const float* bih  = (z & 1) ? bihr : bihf;
  const float* bhh  = (z & 1) ? bhhr : bhhf;

  int m0 = blockIdx.y * 128, n0 = blockIdx.x * 128;
  int tid = threadIdx.x, lane = tid & 31, warp = tid >> 5;
  int wm = warp & 3, wn = warp >> 2;
  int gid = lane >> 2, tig = lane & 3;

  int ar = tid >> 1, ac = (tid & 1) * 8;
  const float* aSrc = emb + (size_t)toks[m0 + ar] * E_DIM + ac;
  const float* bSrc = W   + (size_t)(n0 + ar) * E_DIM + ac;

  float c[2][8][4];
  #pragma unroll
  for (int mi = 0; mi < 2; mi++)
    #pragma unroll
    for (int ni = 0; ni < 8; ni++)
      #pragma unroll
      for (int q = 0; q < 4; q++) c[mi][ni][q] = 0.f;

  for (int k0 = 0; k0 < E_DIM; k0 += 16) {
    float4 av0 = *(const float4*)(aSrc + k0);
    float4 av1 = *(const float4*)(aSrc + k0 + 4);
    float4 bv0 = *(const float4*)(bSrc + k0);
    float4 bv1 = *(const float4*)(bSrc + k0 + 4);
    __syncthreads();
    As[ar][ac+0]=av0.x; As[ar][ac+1]=av0.y; As[ar][ac+2]=av0.z; As[ar][ac+3]=av0.w;
    As[ar][ac+4]=av1.x; As[ar][ac+5]=av1.y; As[ar][ac+6]=av1.z; As[ar][ac+7]=av1.w;
    Bs[ar][ac+0]=bv0.x; Bs[ar][ac+1]=bv0.y; Bs[ar][ac+2]=bv0.z; Bs[ar][ac+3]=bv0.w;
    Bs[ar][ac+4]=bv1.x; Bs[ar][ac+5]=bv1.y; Bs[ar][ac+6]=bv1.z; Bs[ar][ac+7]=bv1.w;
    __syncthreads();

    #pragma unroll
    for (int kk = 0; kk < 16; kk += 8) {
      unsigned a[2][4];
      #pragma unroll
      for (int mi = 0; mi < 2; mi++) {
        int r0 = wm * 32 + mi * 16 + gid;
        a[mi][0] = tf32_of(As[r0    ][kk + tig    ]);
        a[mi][1] = tf32_of(As[r0 + 8][kk + tig    ]);
        a[mi][2] = tf32_of(As[r0    ][kk + tig + 4]);
        a[mi][3] = tf32_of(As[r0 + 8][kk + tig + 4]);
      }
      unsigned b[8][2];
      #pragma unroll
      for (int ni = 0; ni < 8; ni++) {
        int cc = wn * 64 + ni * 8 + gid;
        b[ni][0] = tf32_of(Bs[cc][kk + tig    ]);
        b[ni][1] = tf32_of(Bs[cc][kk + tig + 4]);
      }
      #pragma unroll
      for (int mi = 0; mi < 2; mi++)
        #pragma unroll
        for (int ni = 0; ni < 8; ni++)
          mma_tf32(c[mi][ni], a[mi], b[ni]);
    }
  }

  #pragma unroll
  for (int mi = 0; mi < 2; mi++) {
    int row = m0 + wm * 32 + mi * 16 + gid;
    #pragma unroll
    for (int ni = 0; ni < 8; ni++) {
      int colb = n0 + wn * 64 + ni * 8 + 2 * tig;
      float bb0 = bih[colb]     + (colb     < 2 * H_DIM ? bhh[colb]     : 0.f);
      float bb1 = bih[colb + 1] + (colb + 1 < 2 * H_DIM ? bhh[colb + 1] : 0.f);
      float2 v0 = make_float2(c[mi][ni][0] + bb0, c[mi][ni][1] + bb1);
      float2 v1 = make_float2(c[mi][ni][2] + bb0, c[mi][ni][3] + bb1);
      *(float2*)&g_gx[z][row    ][colb] = v0;
      *(float2*)&g_gx[z][row + 8][colb] = v1;
    }
  }
}

// ---------------- persistent GRU recurrence, sentence-staggered ----------------
// 128 CTAs: d = cta/64, outputs [i0, i0+16). Two phases per step (sentence A, B)
// with separate flag sets; the wait for chain s is hidden behind the other
// chain's compute. Warps 8/9 are dedicated pollers publishing step counters to
// SMEM. Weights: k-chunks 0..5 in registers, 6..7 in SMEM.
extern __shared__ float s_dyn[];

__global__ __launch_bounds__(RNN_THREADS, 1) void rnn_kernel(
    const float* __restrict__ whf, const float* __restrict__ whr,
    const float* __restrict__ bhhf, const float* __restrict__ bhhr) {
  float* sWp = s_dyn;                          // 48 rows * 256 (k=768..1023)
  float* sH  = sWp + 48 * 256;                 // [2][H_DIM] staging
  float* sGh = sH + 2 * H_DIM;                 // [2][48]
  unsigned* sGo = (unsigned*)(sGh + 96);       // [2] counters, 128B apart

  int cta = blockIdx.x;
  int d   = cta >> 6;
  int i0  = (cta & 63) * NIDX;
  const float* Wh = d ? whr : whf;
  int tid = threadIdx.x, lane = tid & 31, warp = tid >> 5;

  if (tid == 0) { sGo[0] = 0u; sGo[32] = 0u; }

  // smem weights: k-chunks 6..7 (256 floats) of all 48 rows
  for (int r = 0; r < 48; r++) {
    int g = r >> 4, li = r & 15;
    const float* src = Wh + (size_t)(g * H_DIM + i0 + li) * H_DIM + 768;
    for (int k = tid; k < 256; k += RNN_THREADS) sWp[r * 256 + k] = src[k];
  }

  // register weights (compute warps): rows r = warp + rr*8, chunks 0..5
  ull wreg[6][6][2];
  if (warp < 8) {
    #pragma unroll
    for (int rr = 0; rr < 6; rr++) {
      int r = warp + rr * 8, g = r >> 4, li = r & 15;
      const float* src = Wh + (size_t)(g * H_DIM + i0 + li) * H_DIM;
      #pragma unroll
      for (int jj = 0; jj < 6; jj++) {
        const ull* p = (const ull*)(src + jj * 128 + lane * 4);
        wreg[rr][jj][0] = p[0];
        wreg[rr][jj][1] = p[1];
      }
    }
  }

  float bhn = 0.f, hold0 = 0.f, hold1 = 0.f;
  if (warp == 0 && lane < 16) {
    bhn   = (d ? bhhr : bhhf)[2 * H_DIM + i0 + lane];
    hold0 = g_h[0][d][0][i0 + lane];
    hold1 = g_h[0][d][1][i0 + lane];
  }

  __syncthreads();   // setup complete

  if (warp >= 8) {
    // ---- dedicated poller for sentence s ----
    int s = warp - 8;
    const unsigned* fl = &g_flag[s][(d * 64) * 32];
    const unsigned* fp0 = fl + lane * 32;
    const unsigned* fp1 = fl + (lane + 32) * 32;
    unsigned* go = sGo + s * 32;
    for (unsigned t = 1; t < L_SEQ; t++) {
      for (;;) {
        unsigned a = ld_acq(fp0);
        unsigned b = ld_acq(fp1);
        if (__all_sync(0xffffffffu, a >= t && b >= t)) break;
      }
      if (lane == 0) st_rel_cta(go, t);
    }
    return;
  }

  // ---- compute warps ----
  bool isGate = (warp == 0 && lane < 16);

  for (int t = 0; t < L_SEQ; t++) {
    int cur = t & 1, nxt = cur ^ 1;

    #pragma unroll
    for (int s = 0; s < 2; s++) {
      float* sHs  = sH + s * H_DIM;
      float* sGhS = sGh + s * 48;

      // warp 0: issue gx loads before spinning (latency hidden)
      float gxr = 0.f, gxz = 0.f, gxn = 0.f;
      if (isGate) {
        int trow = d ? (L_SEQ - 1 - t) : t;
        const float* gxp = &g_gx[s * 2 + d][trow][0];
        gxr = __ldg(gxp + i0 + lane);
        gxz = __ldg(gxp + H_DIM + i0 + lane);
        gxn = __ldg(gxp + 2 * H_DIM + i0 + lane);
      }

      // wait until chain s reached step t (poller publishes to smem)
      if (t) {
        const unsigned* go = sGo + s * 32;
        unsigned tgt = (unsigned)t;
        while (ld_acq_cta(go) < tgt) { }
      }

      // stage h_s(t): 256 threads x 1 float4 = 4KB
      {
        const float4* src = (const float4*)&g_h[cur][d][s][0];
        ((float4*)sHs)[tid] = ldcg_f4(src + tid);
      }
      bar2();

      // dots: 6 rows/warp, chunks 0..5 from regs, 6..7 from smem
      ull aa0[6], aa1[6];
      #pragma unroll
      for (int rr = 0; rr < 6; rr++) { aa0[rr] = 0; aa1[rr] = 0; }
      #pragma unroll
      for (int jj = 0; jj < 6; jj++) {
        ulonglong2 h2 = *(ulonglong2*)(sHs + jj * 128 + lane * 4);
        #pragma unroll
        for (int rr = 0; rr < 6; rr++) {
          ffma2(aa0[rr], wreg[rr][jj][0], h2.x);
          ffma2(aa1[rr], wreg[rr][jj][1], h2.y);
        }
      }
      #pragma unroll
      for (int jj = 0; jj < 2; jj++) {
        ulonglong2 h2 = *(ulonglong2*)(sHs + (6 + jj) * 128 + lane * 4);
        #pragma unroll
        for (int rr = 0; rr < 6; rr++) {
          ulonglong2 w = *(const ulonglong2*)(sWp + (warp + rr * 8) * 256 + jj * 128 + lane * 4);
          ffma2(aa0[rr], w.x, h2.x);
          ffma2(aa1[rr], w.y, h2.y);
        }
      }
      #pragma unroll
      for (int rr = 0; rr < 6; rr++) {
        float v = pairsum(aa0[rr]) + pairsum(aa1[rr]);
        #pragma unroll
        for (int off = 16; off > 0; off >>= 1)
          v += __shfl_xor_sync(0xffffffffu, v, off);
        if (lane == 0) sGhS[warp + rr * 8] = v;
      }
      bar2();   // sGh[s] ready

      // warp 0: gates + publish; other warps proceed to next phase
      if (warp == 0) {
        if (lane < 16) {
          float ghr = sGhS[lane];
          float ghz = sGhS[16 + lane];
          float ghn = sGhS[32 + lane];
          float r_ = sigm(gxr + ghr);
          float z_ = sigm(gxz + ghz);
          float ag = gxn + r_ * (ghn + bhn);
          ag = fminf(fmaxf(ag, -15.f), 15.f);
          float e = __expf(-2.f * ag);
          float n_ = (1.f - e) / (1.f + e);
          float hprev = s ? hold1 : hold0;
          float hnew = (1.f - z_) * n_ + z_ * hprev;
          if (s) hold1 = hnew; else hold0 = hnew;
          g_h[nxt][d][s][i0 + lane] = hnew;
        }
        __syncwarp();
        if (lane == 0) st_rel(&g_flag[s][cta * 32], (unsigned)(t + 1));
      }
    }
  }
}

// ---------------- head ----------------
__global__ __launch_bounds__(256) void head1(const float* __restrict__ W2,
                                             const float* __restrict__ b2) {
  __shared__ float ht[H_DIM];
  __shared__ float wsum[8];
  int j = blockIdx.x, tid = threadIdx.x, lane = tid & 31, warp = tid >> 5;
  const float* fA = (j < 2) ? &g_h[0][0][0][0] : &g_h[0][1][0][0];
  const float* fB = (j < 2) ? &g_h[0][0][1][0] : &g_h[0][1][1][0];
  for (int k = tid; k < H_DIM; k += 256) {
    float a = fA[k], b = fB[k];
    ht[k] = (j & 1) ? a * b : fabsf(a - b);
  }
  __syncthreads();

  int tbase = blockIdx.y * 64;
  float acc = 0.f;
  for (int t = tbase + warp; t < tbase + 64; t += 8) {
    const float4* w = (const float4*)(W2 + (size_t)t * H_DIM) + lane;
    const float4* h4 = (const float4*)ht + lane;
    float dsum = 0.f;
    #pragma unroll
    for (int q = 0; q < 8; q++) {
      float4 wv = __ldg(w + q * 32);
      float4 hv = h4[q * 32];
      dsum += wv.x * hv.x + wv.y * hv.y + wv.z * hv.z + wv.w * hv.w;
    }
    #pragma unroll
    for (int off = 16; off > 0; off >>= 1)
      dsum += __shfl_xor_sync(0xffffffffu, dsum, off);
    if (lane == 0) acc += fmaxf(dsum + b2[t], 0.f);
  }
  if (lane == 0) wsum[warp] = acc;
  __syncthreads();
  if (tid == 0) {
    float s = 0.f;
    #pragma unroll
    for (int w = 0; w < 8; w++) s += wsum[w];
    atomicAdd(&g_hs[j], s);
  }
}

__global__ void head2(const float* __restrict__ Wl, const float* __restrict__ bl,
                      float* __restrict__ out) {
  float s = bl[0];
  #pragma unroll
  for (int j = 0; j < 4; j++) s += g_hs[j] * Wl[j];
  out[0] = 1.f / (1.f + __expf(-s));
}

// ---------------- launch ----------------
extern "C" void kernel_launch(void* const* d_in, const int* in_sizes, int n_in,
                              void* d_out, int out_size) {
  const int*   sentA  = (const int*)d_in[0];
  const int*   sentB  = (const int*)d_in[1];
  const float* hidden = (const float*)d_in[2];
  const float* emb    = (const float*)d_in[3];
  const float* w_ih_f = (const float*)d_in[4];
  const float* w_hh_f = (const float*)d_in[5];
  const float* b_ih_f = (const float*)d_in[6];
  const float* b_hh_f = (const float*)d_in[7];
  const float* w_ih_r = (const float*)d_in[8];
  const float* w_hh_r = (const float*)d_in[9];
  const float* b_ih_r = (const float*)d_in[10];
  const float* b_hh_r = (const float*)d_in[11];
  const float* W2     = (const float*)d_in[12];
  const float* b2     = (const float*)d_in[13];
  const float* Wl     = (const float*)d_in[14];
  const float* bl     = (const float*)d_in[15];
  float* out = (float*)d_out;

  int rnn_smem = (48 * 256 + 2 * H_DIM + 96 + 64) * (int)sizeof(float);
  cudaFuncSetAttribute(rnn_kernel, cudaFuncAttributeMaxDynamicSharedMemorySize, rnn_smem);

  init_kernel<<<32, 256>>>(hidden);

  dim3 ggrid(H3 / 128, L_SEQ / 128, 4);
  gemm_gx<<<ggrid, 256>>>(sentA, sentB, emb, w_ih_f, w_ih_r,
                          b_ih_f, b_hh_f, b_ih_r, b_hh_r);

  rnn_kernel<<<RNN_NCTA, RNN_THREADS, rnn_smem>>>(w_hh_f, w_hh_r, b_hh_f, b_hh_r);

  head1<<<dim3(4, 8), 256>>>(W2, b2);
  head2<<<1, 1>>>(Wl, bl, out);
}

// round 8
// speedup vs baseline: 1.5349x; 1.5349x over previous
#include <cuda_runtime.h>
#include <cuda_bf16.h>
#include <cstdint>
#include <math.h>

#define L_SEQ 4096
#define H_DIM 1024
#define E_DIM 1024
#define H3    3072
#define T_DIM 512

#define RNN_NCTA 128
#define RNN_THREADS 256

typedef unsigned long long ull;

// ---------------- device scratch ----------------
__device__ float g_gx[4][L_SEQ][H3];          // [sent*2+dir][t][3H]
__device__ float g_h[2][2][2][H_DIM];         // [buf][dir][sent][H]
__device__ float g_hs[4];
__device__ unsigned int g_flag[RNN_NCTA * 32];   // per-CTA, 128B padded

// ---------------- helpers ----------------
__device__ __forceinline__ unsigned tf32_of(float f) {
  unsigned r; asm("cvt.rna.tf32.f32 %0, %1;" : "=r"(r) : "f"(f)); return r;
}
__device__ __forceinline__ void mma_tf32(float* c, const unsigned* a, const unsigned* b) {
  asm volatile("mma.sync.aligned.m16n8k8.row.col.f32.tf32.tf32.f32 "
    "{%0,%1,%2,%3},{%4,%5,%6,%7},{%8,%9},{%0,%1,%2,%3};"
    : "+f"(c[0]), "+f"(c[1]), "+f"(c[2]), "+f"(c[3])
    : "r"(a[0]), "r"(a[1]), "r"(a[2]), "r"(a[3]), "r"(b[0]), "r"(b[1]));
}
__device__ __forceinline__ float sigm(float x) { return 1.f / (1.f + __expf(-x)); }

__device__ __forceinline__ unsigned ld_acq(const unsigned* p) {
  unsigned v;
  asm volatile("ld.acquire.gpu.u32 %0, [%1];" : "=r"(v) : "l"(p) : "memory");
  return v;
}
__device__ __forceinline__ void st_rel(unsigned* p, unsigned v) {
  asm volatile("st.release.gpu.u32 [%0], %1;" :: "l"(p), "r"(v) : "memory");
}
__device__ __forceinline__ float4 ldcg_f4(const float4* p) {
  float4 v;
  asm volatile("ld.global.cg.v4.f32 {%0,%1,%2,%3}, [%4];"
    : "=f"(v.x), "=f"(v.y), "=f"(v.z), "=f"(v.w) : "l"(p));
  return v;
}
__device__ __forceinline__ void bar3_64() {
  asm volatile("bar.sync 3, 64;" ::: "memory");
}

// ---------------- init ----------------
__global__ void init_kernel(const float* __restrict__ hidden) {
  int i = blockIdx.x * blockDim.x + threadIdx.x;
  if (i < RNN_NCTA * 32) g_flag[i] = 0u;
  if (i < 4) g_hs[i] = 0.f;
  if (i < 2 * H_DIM) {
    int d = i / H_DIM, j = i % H_DIM;
    g_h[0][d][0][j] = hidden[i];
    g_h[0][d][1][j] = hidden[i];
  }
}

// ---------------- gx GEMM ----------------
__global__ __launch_bounds__(256) void gemm_gx(
    const int* __restrict__ sA, const int* __restrict__ sB,
    const float* __restrict__ emb,
    const float* __restrict__ wf, const float* __restrict__ wr,
    const float* __restrict__ bihf, const float* __restrict__ bhhf,
    const float* __restrict__ bihr, const float* __restrict__ bhhr) {
  __shared__ float As[128][17];
  __shared__ float Bs[128][17];

  int z = blockIdx.z;
  const int*   toks = (z >> 1) ? sB : sA;
  const float* W    = (z & 1) ? wr   : wf;
  const float* bih  = (z & 1) ? bihr : bihf;
  const float* bhh  = (z & 1) ? bhhr : bhhf;

  int m0 = blockIdx.y * 128, n0 = blockIdx.x * 128;
  int tid = threadIdx.x, lane = tid & 31, warp = tid >> 5;
  int wm = warp & 3, wn = warp >> 2;
  int gid = lane >> 2, tig = lane & 3;

  int ar = tid >> 1, ac = (tid & 1) * 8;
  const float* aSrc = emb + (size_t)toks[m0 + ar] * E_DIM + ac;
  const float* bSrc = W   + (size_t)(n0 + ar) * E_DIM + ac;

  float c[2][8][4];
  #pragma unroll
  for (int mi = 0; mi < 2; mi++)
    #pragma unroll
    for (int ni = 0; ni < 8; ni++)
      #pragma unroll
      for (int q = 0; q < 4; q++) c[mi][ni][q] = 0.f;

  for (int k0 = 0; k0 < E_DIM; k0 += 16) {
    float4 av0 = *(const float4*)(aSrc + k0);
    float4 av1 = *(const float4*)(aSrc + k0 + 4);
    float4 bv0 = *(const float4*)(bSrc + k0);
    float4 bv1 = *(const float4*)(bSrc + k0 + 4);
    __syncthreads();
    As[ar][ac+0]=av0.x; As[ar][ac+1]=av0.y; As[ar][ac+2]=av0.z; As[ar][ac+3]=av0.w;
    As[ar][ac+4]=av1.x; As[ar][ac+5]=av1.y; As[ar][ac+6]=av1.z; As[ar][ac+7]=av1.w;
    Bs[ar][ac+0]=bv0.x; Bs[ar][ac+1]=bv0.y; Bs[ar][ac+2]=bv0.z; Bs[ar][ac+3]=bv0.w;
    Bs[ar][ac+4]=bv1.x; Bs[ar][ac+5]=bv1.y; Bs[ar][ac+6]=bv1.z; Bs[ar][ac+7]=bv1.w;
    __syncthreads();

    #pragma unroll
    for (int kk = 0; kk < 16; kk += 8) {
      unsigned a[2][4];
      #pragma unroll
      for (int mi = 0; mi < 2; mi++) {
        int r0 = wm * 32 + mi * 16 + gid;
        a[mi][0] = tf32_of(As[r0    ][kk + tig    ]);
        a[mi][1] = tf32_of(As[r0 + 8][kk + tig    ]);
        a[mi][2] = tf32_of(As[r0    ][kk + tig + 4]);
        a[mi][3] = tf32_of(As[r0 + 8][kk + tig + 4]);
      }
      unsigned b[8][2];
      #pragma unroll
      for (int ni = 0; ni < 8; ni++) {
        int cc = wn * 64 + ni * 8 + gid;
        b[ni][0] = tf32_of(Bs[cc][kk + tig    ]);
        b[ni][1] = tf32_of(Bs[cc][kk + tig + 4]);
      }
      #pragma unroll
      for (int mi = 0; mi < 2; mi++)
        #pragma unroll
        for (int ni = 0; ni < 8; ni++)
          mma_tf32(c[mi][ni], a[mi], b[ni]);
    }
  }

  #pragma unroll
  for (int mi = 0; mi < 2; mi++) {
    int row = m0 + wm * 32 + mi * 16 + gid;
    #pragma unroll
    for (int ni = 0; ni < 8; ni++) {
      int colb = n0 + wn * 64 + ni * 8 + 2 * tig;
      float bb0 = bih[colb]     + (colb     < 2 * H_DIM ? bhh[colb]     : 0.f);
      float bb1 = bih[colb + 1] + (colb + 1 < 2 * H_DIM ? bhh[colb + 1] : 0.f);
      float2 v0 = make_float2(c[mi][ni][0] + bb0, c[mi][ni][1] + bb1);
      float2 v1 = make_float2(c[mi][ni][2] + bb0, c[mi][ni][3] + bb1);
      *(float2*)&g_gx[z][row    ][colb] = v0;
      *(float2*)&g_gx[z][row + 8][colb] = v1;
    }
  }
}

// ---------------- persistent GRU recurrence (tensor-core dots) ----------------
// 128 CTAs: d = cta/64, outputs [i0, i0+16) -> 48 gate rows = 3 m16 tiles.
// All w_hh held as tf32 mma A-fragments in registers (48 mma/warp, k=128/warp).
// Per step: threads 0-63 poll flags + bar(64) + stage h (8KB smem); all warps
// mma (B-frags from smem h); STS D partials; warp 0 reduces (r/z/n land in the
// right lanes), gates, STG h, release.
extern __shared__ float s_dyn[];

__global__ __launch_bounds__(RNN_THREADS, 1) void rnn_kernel(
    const float* __restrict__ whf, const float* __restrict__ whr,
    const float* __restrict__ bhhf, const float* __restrict__ bhhr) {
  float* sH    = s_dyn;            // 2048 floats: [sent][1024]
  float* sPart = sH + 2048;        // 8 warps * 96

  int cta = blockIdx.x;
  int d   = cta >> 6;
  int i0  = (cta & 63) * 16;
  const float* Wh = d ? whr : whf;
  int tid = threadIdx.x, lane = tid & 31, warp = tid >> 5;
  int gid = lane >> 2, tig = lane & 3;
  int kbase = warp * 128;

  // ---- load all weight A-fragments into registers (setup) ----
  unsigned aw[3][16][4];
  #pragma unroll
  for (int g = 0; g < 3; g++) {
    const float* w0 = Wh + (size_t)(g * H_DIM + i0 + gid) * H_DIM;
    const float* w8 = w0 + 8 * (size_t)H_DIM;
    #pragma unroll
    for (int s = 0; s < 16; s++) {
      int col = kbase + s * 8 + tig;
      aw[g][s][0] = tf32_of(__ldg(w0 + col));
      aw[g][s][1] = tf32_of(__ldg(w8 + col));
      aw[g][s][2] = tf32_of(__ldg(w0 + col + 4));
      aw[g][s][3] = tf32_of(__ldg(w8 + col + 4));
    }
  }

  // gate state (warp 0): lane -> (sent = lane&1, li = lane>>1)
  float bhn = 0.f, hold = 0.f;
  if (warp == 0) {
    int sent = lane & 1, li = lane >> 1;
    bhn  = (d ? bhhr : bhhf)[2 * H_DIM + i0 + li];
    hold = g_h[0][d][sent][i0 + li];
  }
  const unsigned* flagbase = g_flag + (d * 64) * 32;
  unsigned* myflag = g_flag + cta * 32;

  __syncthreads();

  for (int t = 0; t < L_SEQ; t++) {
    int cur = t & 1, nxt = cur ^ 1;

    // warp 0: issue gx(t) loads before anything blocks (consumed at gates)
    float gxr = 0.f, gxz = 0.f, gxn = 0.f;
    if (warp == 0) {
      int sent = lane & 1, li = lane >> 1;
      int trow = d ? (L_SEQ - 1 - t) : t;
      const float* gxp = &g_gx[sent * 2 + d][trow][0];
      gxr = __ldg(gxp + i0 + li);
      gxz = __ldg(gxp + H_DIM + i0 + li);
      gxn = __ldg(gxp + 2 * H_DIM + i0 + li);
    }

    // threads 0-63: poll 1 flag each, bar(64) so ALL flags verified, stage h
    if (tid < 64) {
      if (t) {
        const unsigned* fp = flagbase + tid * 32;
        unsigned tgt = (unsigned)t;
        while (ld_acq(fp) < tgt) { }
      }
      bar3_64();
      const float4* src = (const float4*)&g_h[cur][d][0][0];  // 512 float4
      float4* dst = (float4*)sH;
      #pragma unroll
      for (int q = 0; q < 8; q++) dst[tid + q * 64] = ldcg_f4(src + tid + q * 64);
    }
    __syncthreads();   // sH ready

    // ---- tensor-core dots: 3 tiles x 16 ksteps ----
    float cfr[3][4];
    #pragma unroll
    for (int g = 0; g < 3; g++)
      #pragma unroll
      for (int q = 0; q < 4; q++) cfr[g][q] = 0.f;

    #pragma unroll
    for (int s = 0; s < 16; s++) {
      float b0f = 0.f, b1f = 0.f;
      if (gid < 2) {
        const float* hp = sH + gid * H_DIM + kbase + s * 8 + tig;
        b0f = hp[0];
        b1f = hp[4];
      }
      unsigned b[2] = { tf32_of(b0f), tf32_of(b1f) };
      #pragma unroll
      for (int g = 0; g < 3; g++) mma_tf32(cfr[g], aw[g][s], b);
    }

    // D layout: tig==0 lanes hold cols 0,1 (sent A,B); rows gid and gid+8.
    if (tig == 0) {
      float* pp = sPart + warp * 96;
      #pragma unroll
      for (int g = 0; g < 3; g++) {
        int r0 = g * 16 + gid;
        *(float2*)(pp + r0 * 2)       = make_float2(cfr[g][0], cfr[g][1]);
        *(float2*)(pp + (r0 + 8) * 2) = make_float2(cfr[g][2], cfr[g][3]);
      }
    }
    __syncthreads();   // sPart ready

    // warp 0: reduce 8 partials; o = row*2+sent, gate lane L needs o = L, L+32, L+64
    if (warp == 0) {
      float vr = 0.f, vz = 0.f, vn = 0.f;
      #pragma unroll
      for (int w = 0; w < 8; w++) {
        const float* pp = sPart + w * 96;
        vr += pp[lane];
        vz += pp[lane + 32];
        vn += pp[lane + 64];
      }
      float r_ = sigm(gxr + vr);
      float z_ = sigm(gxz + vz);
      float ag = gxn + r_ * (vn + bhn);
      ag = fminf(fmaxf(ag, -15.f), 15.f);
      float e = __expf(-2.f * ag);
      float n_ = (1.f - e) / (1.f + e);
      float hnew = (1.f - z_) * n_ + z_ * hold;
      hold = hnew;
      int sent = lane & 1, li = lane >> 1;
      g_h[nxt][d][sent][i0 + li] = hnew;
      __syncwarp();
      if (lane == 0) st_rel(myflag, (unsigned)(t + 1));
    }
  }
}

// ---------------- head ----------------
__global__ __launch_bounds__(256) void head1(const float* __restrict__ W2,
                                             const float* __restrict__ b2) {
  __shared__ float ht[H_DIM];
  __shared__ float wsum[8];
  int j = blockIdx.x, tid = threadIdx.x, lane = tid & 31, warp = tid >> 5;
  const float* fA = (j < 2) ? &g_h[0][0][0][0] : &g_h[0][1][0][0];
  const float* fB = (j < 2) ? &g_h[0][0][1][0] : &g_h[0][1][1][0];
  for (int k = tid; k < H_DIM; k += 256) {
    float a = fA[k], b = fB[k];
    ht[k] = (j & 1) ? a * b : fabsf(a - b);
  }
  __syncthreads();

  int tbase = blockIdx.y * 64;
  float acc = 0.f;
  for (int t = tbase + warp; t < tbase + 64; t += 8) {
    const float4* w = (const float4*)(W2 + (size_t)t * H_DIM) + lane;
    const float4* h4 = (const float4*)ht + lane;
    float dsum = 0.f;
    #pragma unroll
    for (int q = 0; q < 8; q++) {
      float4 wv = __ldg(w + q * 32);
      float4 hv = h4[q * 32];
      dsum += wv.x * hv.x + wv.y * hv.y + wv.z * hv.z + wv.w * hv.w;
    }
    #pragma unroll
    for (int off = 16; off > 0; off >>= 1)
      dsum += __shfl_xor_sync(0xffffffffu, dsum, off);
    if (lane == 0) acc += fmaxf(dsum + b2[t], 0.f);
  }
  if (lane == 0) wsum[warp] = acc;
  __syncthreads();
  if (tid == 0) {
    float s = 0.f;
    #pragma unroll
    for (int w = 0; w < 8; w++) s += wsum[w];
    atomicAdd(&g_hs[j], s);
  }
}

__global__ void head2(const float* __restrict__ Wl, const float* __restrict__ bl,
                      float* __restrict__ out) {
  float s = bl[0];
  #pragma unroll
  for (int j = 0; j < 4; j++) s += g_hs[j] * Wl[j];
  out[0] = 1.f / (1.f + __expf(-s));
}

// ---------------- launch ----------------
extern "C" void kernel_launch(void* const* d_in, const int* in_sizes, int n_in,
                              void* d_out, int out_size) {
  const int*   sentA  = (const int*)d_in[0];
  const int*   sentB  = (const int*)d_in[1];
  const float* hidden = (const float*)d_in[2];
  const float* emb    = (const float*)d_in[3];
  const float* w_ih_f = (const float*)d_in[4];
  const float* w_hh_f = (const float*)d_in[5];
  const float* b_ih_f = (const float*)d_in[6];
  const float* b_hh_f = (const float*)d_in[7];
  const float* w_ih_r = (const float*)d_in[8];
  const float* w_hh_r = (const float*)d_in[9];
  const float* b_ih_r = (const float*)d_in[10];
  const float* b_hh_r = (const float*)d_in[11];
  const float* W2     = (const float*)d_in[12];
  const float* b2     = (const float*)d_in[13];
  const float* Wl     = (const float*)d_in[14];
  const float* bl     = (const float*)d_in[15];
  float* out = (float*)d_out;

  int rnn_smem = (2048 + 8 * 96) * (int)sizeof(float);
  cudaFuncSetAttribute(rnn_kernel, cudaFuncAttributeMaxDynamicSharedMemorySize, rnn_smem);

  init_kernel<<<32, 256>>>(hidden);

  dim3 ggrid(H3 / 128, L_SEQ / 128, 4);
  gemm_gx<<<ggrid, 256>>>(sentA, sentB, emb, w_ih_f, w_ih_r,
                          b_ih_f, b_hh_f, b_ih_r, b_hh_r);

  rnn_kernel<<<RNN_NCTA, RNN_THREADS, rnn_smem>>>(w_hh_f, w_hh_r, b_hh_f, b_hh_r);

  head1<<<dim3(4, 8), 256>>>(W2, b2);
  head2<<<1, 1>>>(Wl, bl, out);
}